// round 3
// baseline (speedup 1.0000x reference)
#include <cuda_runtime.h>
#include <cuda_bf16.h>
#include <cstdint>
#include <cstddef>

// ---------------------------------------------------------------------------
// Problem dims
// ---------------------------------------------------------------------------
constexpr int kB  = 4096;   // batch
constexpr int kIN = 1024;   // input dim
constexpr int kV  = 48;     // vocab (num MLPs)
constexpr int kH  = 512;    // hidden
constexpr int kO  = 64;     // out per MLP

// ---------------------------------------------------------------------------
// Device scratch: bf16 hi/lo split operands + intermediates
// ---------------------------------------------------------------------------
__device__ __align__(1024) __nv_bfloat16 g_Xh [(size_t)kB * kIN];
__device__ __align__(1024) __nv_bfloat16 g_Xl [(size_t)kB * kIN];
__device__ __align__(1024) __nv_bfloat16 g_W1h[(size_t)kV * kH * kIN];  // [v][h][i]
__device__ __align__(1024) __nv_bfloat16 g_W1l[(size_t)kV * kH * kIN];
__device__ __align__(1024) __nv_bfloat16 g_W2h[(size_t)kV * kH * kH];   // [v][k][h]
__device__ __align__(1024) __nv_bfloat16 g_W2l[(size_t)kV * kH * kH];
__device__ __align__(1024) __nv_bfloat16 g_W3h[(size_t)kV * kO * kH];   // [v][o][k]
__device__ __align__(1024) __nv_bfloat16 g_W3l[(size_t)kV * kO * kH];
__device__ __align__(1024) __nv_bfloat16 g_H1h[(size_t)kV * kB * kH];   // [v][m][h]
__device__ __align__(1024) __nv_bfloat16 g_H1l[(size_t)kV * kB * kH];
__device__ __align__(1024) __nv_bfloat16 g_H2h[(size_t)kV * kB * kH];
__device__ __align__(1024) __nv_bfloat16 g_H2l[(size_t)kV * kB * kH];

// ---------------------------------------------------------------------------
// PTX helpers — baseline (non-'a') PTX only: cp.async / ldmatrix / mma.sync
// ---------------------------------------------------------------------------
#define DINLINE __device__ __forceinline__

DINLINE uint32_t smem_u32(const void* p) {
    uint32_t a;
    asm("{ .reg .u64 t; cvta.to.shared.u64 t, %1; cvt.u32.u64 %0, t; }" : "=r"(a) : "l"(p));
    return a;
}
DINLINE uint32_t swz(uint32_t o) { return o ^ ((o >> 3) & 0x70); }

DINLINE void cp16(uint32_t dst, const void* src) {
    asm volatile("cp.async.cg.shared.global [%0], [%1], 16;" :: "r"(dst), "l"(src));
}
DINLINE void cp_commit() { asm volatile("cp.async.commit_group;" ::: "memory"); }
template <int N> DINLINE void cp_wait() {
    asm volatile("cp.async.wait_group %0;" :: "n"(N) : "memory");
}

DINLINE void ldsm4(uint32_t& r0, uint32_t& r1, uint32_t& r2, uint32_t& r3, uint32_t a) {
    asm volatile("ldmatrix.sync.aligned.m8n8.x4.shared.b16 {%0,%1,%2,%3}, [%4];"
                 : "=r"(r0), "=r"(r1), "=r"(r2), "=r"(r3) : "r"(a));
}

DINLINE void mma16816(float* d, const uint32_t* a, const uint32_t* b) {
    asm volatile(
        "mma.sync.aligned.m16n8k16.row.col.f32.bf16.bf16.f32 "
        "{%0,%1,%2,%3}, {%4,%5,%6,%7}, {%8,%9}, {%0,%1,%2,%3};"
        : "+f"(d[0]), "+f"(d[1]), "+f"(d[2]), "+f"(d[3])
        : "r"(a[0]), "r"(a[1]), "r"(a[2]), "r"(a[3]), "r"(b[0]), "r"(b[1]));
}

// ---------------------------------------------------------------------------
// Prep: fp32 -> bf16 hi/lo split of x
// ---------------------------------------------------------------------------
__global__ void split_x_kernel(const float* __restrict__ x,
                               __nv_bfloat16* __restrict__ oh,
                               __nv_bfloat16* __restrict__ ol) {
    size_t i = (size_t)blockIdx.x * 256 + threadIdx.x;
    float f = x[i];
    __nv_bfloat16 h = __float2bfloat16(f);
    oh[i] = h;
    ol[i] = __float2bfloat16(f - __bfloat162float(h));
}

// ---------------------------------------------------------------------------
// Prep: per-v transpose [v][R][C] -> [v][C][R] + bf16 hi/lo split
// ---------------------------------------------------------------------------
__global__ void transpose_split_kernel(const float* __restrict__ in,
                                       __nv_bfloat16* __restrict__ oh,
                                       __nv_bfloat16* __restrict__ ol,
                                       int R, int C) {
    __shared__ float t[32][33];
    const int v = blockIdx.z;
    const float* src = in + (size_t)v * R * C;
    const size_t ob = (size_t)v * R * C;
    const int tx = threadIdx.x, ty = threadIdx.y;
    const int c = blockIdx.x * 32 + tx;
#pragma unroll
    for (int j = 0; j < 32; j += 8) {
        int r = blockIdx.y * 32 + ty + j;
        t[ty + j][tx] = src[(size_t)r * C + c];
    }
    __syncthreads();
    const int r2 = blockIdx.y * 32 + tx;  // output fast dim (R index)
#pragma unroll
    for (int j = 0; j < 32; j += 8) {
        int c2 = blockIdx.x * 32 + ty + j;  // output row (C index)
        float f = t[tx][ty + j];
        __nv_bfloat16 h = __float2bfloat16(f);
        oh[ob + (size_t)c2 * R + r2] = h;
        ol[ob + (size_t)c2 * R + r2] = __float2bfloat16(f - __bfloat162float(h));
    }
}

// ---------------------------------------------------------------------------
// Batched 3-pass bf16 hi/lo GEMM via mma.sync:
//   D[128 x NT] = A[128 x K] * B[NT x K]^T  (per (m-block, v, n-block) CTA)
//   A = Ah+Al, B = Bh+Bl;  D = Ah*Bh + Ah*Bl + Al*Bh  (fp32 accum)
//   8 warps, warp grid WG_M x WG_N, warp tile (WM*16) x (WN*8)
//   Kc = 64 per chunk, double-buffered cp.async, SW128 swizzle, ldmatrix
// ---------------------------------------------------------------------------
template <int NT, int WG_M, int WG_N, int WM, int WN, bool RELU>
__global__ void __launch_bounds__(256) gemm_kernel(
    const __nv_bfloat16* __restrict__ Ah, const __nv_bfloat16* __restrict__ Al,
    long long aVStride,
    const __nv_bfloat16* __restrict__ Bh, const __nv_bfloat16* __restrict__ Bl,
    int K, int Ndim, int nPerV,
    const float* __restrict__ bias,
    __nv_bfloat16* __restrict__ Oh, __nv_bfloat16* __restrict__ Ol,
    float* __restrict__ out)
{
    static_assert(WG_M * WG_N == 8, "8 warps");
    static_assert(WG_M * WM * 16 == 128, "M tile 128");
    static_assert(WG_N * WN * 8 == NT, "N tile");
    static_assert(WN % 2 == 0, "B ldmatrix pairs");

    extern __shared__ __align__(1024) char smem[];
    const uint32_t sb = smem_u32(smem);
    const int tid = threadIdx.x, wid = tid >> 5, lane = tid & 31;
    const int v  = blockIdx.y / nPerV, nb = blockIdx.y % nPerV;
    const int m0 = blockIdx.x * 128;
    const int n0 = nb * NT;
    const int NC = K >> 6;                 // K chunks of 64

    constexpr int A_SZ = 128 * 128;        // bytes per A part per stage
    constexpr int B_SZ = NT * 128;
    // stage layout: [Ah, Al, Bh, Bl]
    const uint32_t stage0 = sb;
    const uint32_t stage1 = sb + 2 * A_SZ + 2 * B_SZ;
    const uint32_t st[2] = { stage0, stage1 };

    const __nv_bfloat16* A_[2] = { Ah + (size_t)v * aVStride, Al + (size_t)v * aVStride };
    const __nv_bfloat16* B_[2] = { Bh + ((size_t)v * Ndim + n0) * K, Bl + ((size_t)v * Ndim + n0) * K };

    // ---- chunk loader: Kc=64 cols starting at kk into stage s ----
    auto load_chunk = [&](int s, int kk) {
        const uint32_t aH = st[s], aL = st[s] + A_SZ;
        const uint32_t bH = st[s] + 2 * A_SZ, bL = st[s] + 2 * A_SZ + B_SZ;
        for (int idx = tid; idx < 128 * 8; idx += 256) {
            int r = idx >> 3, u = idx & 7;
            uint32_t so = swz((uint32_t)(r * 128 + u * 16));
            size_t go = (size_t)(m0 + r) * K + kk + u * 8;
            cp16(aH + so, A_[0] + go);
            cp16(aL + so, A_[1] + go);
        }
        for (int idx = tid; idx < NT * 8; idx += 256) {
            int r = idx >> 3, u = idx & 7;
            uint32_t so = swz((uint32_t)(r * 128 + u * 16));
            size_t go = (size_t)r * K + kk + u * 8;
            cp16(bH + so, B_[0] + go);
            cp16(bL + so, B_[1] + go);
        }
        cp_commit();
    };

    // warp tile origin
    const int wm = (wid / WG_N) * (WM * 16);
    const int wn = (wid % WG_N) * (WN * 8);

    float d[WM][WN][4];
#pragma unroll
    for (int i = 0; i < WM; i++)
#pragma unroll
        for (int j = 0; j < WN; j++)
#pragma unroll
            for (int q = 0; q < 4; q++) d[i][j][q] = 0.0f;

    load_chunk(0, 0);

    for (int kc = 0; kc < NC; kc++) {
        const int s = kc & 1;
        if (kc + 1 < NC) {
            load_chunk((kc + 1) & 1, (kc + 1) * 64);
            cp_wait<1>();
        } else {
            cp_wait<0>();
        }
        __syncthreads();

        const uint32_t aH = st[s], aL = st[s] + A_SZ;
        const uint32_t bH = st[s] + 2 * A_SZ, bL = st[s] + 2 * A_SZ + B_SZ;

        // A lane address pattern: row = base + (lane&15), k-half = lane>>4
        const int aRow = wm + (lane & 15);
        const int aKh  = (lane >> 4) * 8;
        // B lane address pattern (x4 covers two n8 tiles):
        //   row = base + (lane&7) + ((lane>>4)&1)*8, k-half = ((lane>>3)&1)*8
        const int bRow = wn + (lane & 7) + (((lane >> 4) & 1) << 3);
        const int bKh  = ((lane >> 3) & 1) * 8;

#pragma unroll
        for (int ks = 0; ks < 4; ks++) {
            const int k0 = ks * 16;
            uint32_t ah[WM][4], al[WM][4], bh[WN][2], bl[WN][2];
#pragma unroll
            for (int i = 0; i < WM; i++) {
                uint32_t off = swz((uint32_t)((aRow + i * 16) * 128 + (k0 + aKh) * 2));
                ldsm4(ah[i][0], ah[i][1], ah[i][2], ah[i][3], aH + off);
                ldsm4(al[i][0], al[i][1], al[i][2], al[i][3], aL + off);
            }
#pragma unroll
            for (int j2 = 0; j2 < WN / 2; j2++) {
                uint32_t off = swz((uint32_t)((bRow + j2 * 16) * 128 + (k0 + bKh) * 2));
                ldsm4(bh[2 * j2][0], bh[2 * j2][1], bh[2 * j2 + 1][0], bh[2 * j2 + 1][1], bH + off);
                ldsm4(bl[2 * j2][0], bl[2 * j2][1], bl[2 * j2 + 1][0], bl[2 * j2 + 1][1], bL + off);
            }
            // pass 1: Ah * Bh
#pragma unroll
            for (int i = 0; i < WM; i++)
#pragma unroll
                for (int j = 0; j < WN; j++) mma16816(d[i][j], ah[i], bh[j]);
            // pass 2: Ah * Bl
#pragma unroll
            for (int i = 0; i < WM; i++)
#pragma unroll
                for (int j = 0; j < WN; j++) mma16816(d[i][j], ah[i], bl[j]);
            // pass 3: Al * Bh
#pragma unroll
            for (int i = 0; i < WM; i++)
#pragma unroll
                for (int j = 0; j < WN; j++) mma16816(d[i][j], al[i], bh[j]);
        }
        __syncthreads();   // protect stage buffers before next overwrite
    }

    // ---- epilogue (register fragments, canonical m16n8 D mapping) ----
    const int rBase = lane >> 2;         // 0..7
    const int cBase = (lane & 3) * 2;    // 0,2,4,6
#pragma unroll
    for (int j = 0; j < WN; j++) {
        const int n = n0 + wn + j * 8 + cBase;   // global n (even)
        float bv0 = 0.0f, bv1 = 0.0f;
        if (RELU) {
            bv0 = bias[(size_t)v * kH + n];
            bv1 = bias[(size_t)v * kH + n + 1];
        }
#pragma unroll
        for (int i = 0; i < WM; i++) {
#pragma unroll
            for (int half = 0; half < 2; half++) {
                const int m = m0 + wm + i * 16 + rBase + half * 8;
                float f0 = d[i][j][2 * half];
                float f1 = d[i][j][2 * half + 1];
                if (RELU) {
                    f0 = fmaxf(f0 + bv0, 0.0f);
                    f1 = fmaxf(f1 + bv1, 0.0f);
                    __nv_bfloat16 h0 = __float2bfloat16(f0);
                    __nv_bfloat16 h1 = __float2bfloat16(f1);
                    __nv_bfloat16 l0 = __float2bfloat16(f0 - __bfloat162float(h0));
                    __nv_bfloat16 l1 = __float2bfloat16(f1 - __bfloat162float(h1));
                    uint32_t ph = (uint32_t)__bfloat16_as_ushort(h0) |
                                  ((uint32_t)__bfloat16_as_ushort(h1) << 16);
                    uint32_t pl = (uint32_t)__bfloat16_as_ushort(l0) |
                                  ((uint32_t)__bfloat16_as_ushort(l1) << 16);
                    size_t dst = ((size_t)v * kB + m) * kH + n;
                    *reinterpret_cast<uint32_t*>(Oh + dst) = ph;
                    *reinterpret_cast<uint32_t*>(Ol + dst) = pl;
                } else {
                    size_t dst = (size_t)m * ((size_t)kV * kO) + (size_t)v * kO + n;
                    *reinterpret_cast<float2*>(out + dst) = make_float2(f0, f1);
                }
            }
        }
    }
}

// ---------------------------------------------------------------------------
// Launch
// ---------------------------------------------------------------------------
extern "C" void kernel_launch(void* const* d_in, const int* in_sizes, int n_in,
                              void* d_out, int out_size) {
    const float* x  = (const float*)d_in[0];
    const float* W1 = (const float*)d_in[1];
    const float* b1 = (const float*)d_in[2];
    const float* W2 = (const float*)d_in[3];
    const float* b2 = (const float*)d_in[4];
    const float* W3 = (const float*)d_in[5];
    float* out = (float*)d_out;

    void *pXh, *pXl, *pW1h, *pW1l, *pW2h, *pW2l, *pW3h, *pW3l, *pH1h, *pH1l, *pH2h, *pH2l;
    cudaGetSymbolAddress(&pXh,  g_Xh);  cudaGetSymbolAddress(&pXl,  g_Xl);
    cudaGetSymbolAddress(&pW1h, g_W1h); cudaGetSymbolAddress(&pW1l, g_W1l);
    cudaGetSymbolAddress(&pW2h, g_W2h); cudaGetSymbolAddress(&pW2l, g_W2l);
    cudaGetSymbolAddress(&pW3h, g_W3h); cudaGetSymbolAddress(&pW3l, g_W3l);
    cudaGetSymbolAddress(&pH1h, g_H1h); cudaGetSymbolAddress(&pH1l, g_H1l);
    cudaGetSymbolAddress(&pH2h, g_H2h); cudaGetSymbolAddress(&pH2l, g_H2l);

    // smem: 2 stages * (2*16KB A + 2*NT*128 B)
    constexpr int SMEM_BIG = 2 * (2 * 128 * 128 + 2 * 128 * 128); // NT=128 -> 128KB
    constexpr int SMEM_SM  = 2 * (2 * 128 * 128 + 2 * 64 * 128);  // NT=64  ->  96KB
    cudaFuncSetAttribute((const void*)gemm_kernel<128, 2, 4, 4, 4, true>,
                         cudaFuncAttributeMaxDynamicSharedMemorySize, SMEM_BIG);
    cudaFuncSetAttribute((const void*)gemm_kernel<64, 4, 2, 2, 4, false>,
                         cudaFuncAttributeMaxDynamicSharedMemorySize, SMEM_SM);

    // prep: split x, transpose+split weights
    split_x_kernel<<<(kB * kIN) / 256, 256>>>(x, (__nv_bfloat16*)pXh, (__nv_bfloat16*)pXl);
    dim3 tb(32, 8);
    transpose_split_kernel<<<dim3(kH / 32, kIN / 32, kV), tb>>>(
        W1, (__nv_bfloat16*)pW1h, (__nv_bfloat16*)pW1l, kIN, kH);
    transpose_split_kernel<<<dim3(kH / 32, kH / 32, kV), tb>>>(
        W2, (__nv_bfloat16*)pW2h, (__nv_bfloat16*)pW2l, kH, kH);
    transpose_split_kernel<<<dim3(kO / 32, kH / 32, kV), tb>>>(
        W3, (__nv_bfloat16*)pW3h, (__nv_bfloat16*)pW3l, kH, kO);

    // layer 1: [4096,1024] x [48,512,1024]^T -> H1
    gemm_kernel<128, 2, 4, 4, 4, true><<<dim3(kB / 128, kV * (kH / 128)), 256, SMEM_BIG>>>(
        (const __nv_bfloat16*)pXh, (const __nv_bfloat16*)pXl, 0LL,
        (const __nv_bfloat16*)pW1h, (const __nv_bfloat16*)pW1l,
        kIN, kH, kH / 128, b1,
        (__nv_bfloat16*)pH1h, (__nv_bfloat16*)pH1l, nullptr);

    // layer 2: H1 x [48,512,512]^T -> H2
    gemm_kernel<128, 2, 4, 4, 4, true><<<dim3(kB / 128, kV * (kH / 128)), 256, SMEM_BIG>>>(
        (const __nv_bfloat16*)pH1h, (const __nv_bfloat16*)pH1l, (long long)kB * kH,
        (const __nv_bfloat16*)pW2h, (const __nv_bfloat16*)pW2l,
        kH, kH, kH / 128, b2,
        (__nv_bfloat16*)pH2h, (__nv_bfloat16*)pH2l, nullptr);

    // layer 3: H2 x [48,64,512]^T -> out (fp32, no bias/relu)
    gemm_kernel<64, 4, 2, 2, 4, false><<<dim3(kB / 128, kV), 256, SMEM_SM>>>(
        (const __nv_bfloat16*)pH2h, (const __nv_bfloat16*)pH2l, (long long)kB * kH,
        (const __nv_bfloat16*)pW3h, (const __nv_bfloat16*)pW3l,
        kH, kO, 1, nullptr,
        nullptr, nullptr, out);
}

// round 4
// speedup vs baseline: 2.6118x; 2.6118x over previous
#include <cuda_runtime.h>
#include <cuda_fp16.h>
#include <cstdint>
#include <cstddef>

// ---------------------------------------------------------------------------
// Problem dims
// ---------------------------------------------------------------------------
constexpr int kB  = 4096;   // batch
constexpr int kIN = 1024;   // input dim
constexpr int kV  = 48;     // vocab (num MLPs)
constexpr int kH  = 512;    // hidden
constexpr int kO  = 64;     // out per MLP

// ---------------------------------------------------------------------------
// Device scratch: fp16 operands + intermediates
// ---------------------------------------------------------------------------
__device__ __align__(1024) __half g_X  [(size_t)kB * kIN];
__device__ __align__(1024) __half g_W1 [(size_t)kV * kH * kIN];  // [v][h][i]
__device__ __align__(1024) __half g_W2 [(size_t)kV * kH * kH];   // [v][k][h]
__device__ __align__(1024) __half g_W3 [(size_t)kV * kO * kH];   // [v][o][k]
__device__ __align__(1024) __half g_H1 [(size_t)kV * kB * kH];   // [v][m][h]
__device__ __align__(1024) __half g_H2 [(size_t)kV * kB * kH];

// ---------------------------------------------------------------------------
// PTX helpers — baseline (non-'a') PTX only: cp.async / ldmatrix / mma.sync
// ---------------------------------------------------------------------------
#define DINLINE __device__ __forceinline__

DINLINE uint32_t smem_u32(const void* p) {
    uint32_t a;
    asm("{ .reg .u64 t; cvta.to.shared.u64 t, %1; cvt.u32.u64 %0, t; }" : "=r"(a) : "l"(p));
    return a;
}
DINLINE uint32_t swz(uint32_t o) { return o ^ ((o >> 3) & 0x70); }

DINLINE void cp16(uint32_t dst, const void* src) {
    asm volatile("cp.async.cg.shared.global [%0], [%1], 16;" :: "r"(dst), "l"(src));
}
DINLINE void cp_commit() { asm volatile("cp.async.commit_group;" ::: "memory"); }
template <int N> DINLINE void cp_wait() {
    asm volatile("cp.async.wait_group %0;" :: "n"(N) : "memory");
}

DINLINE void ldsm4(uint32_t& r0, uint32_t& r1, uint32_t& r2, uint32_t& r3, uint32_t a) {
    asm volatile("ldmatrix.sync.aligned.m8n8.x4.shared.b16 {%0,%1,%2,%3}, [%4];"
                 : "=r"(r0), "=r"(r1), "=r"(r2), "=r"(r3) : "r"(a));
}

DINLINE void mma16816(float* d, const uint32_t* a, const uint32_t* b) {
    asm volatile(
        "mma.sync.aligned.m16n8k16.row.col.f32.f16.f16.f32 "
        "{%0,%1,%2,%3}, {%4,%5,%6,%7}, {%8,%9}, {%0,%1,%2,%3};"
        : "+f"(d[0]), "+f"(d[1]), "+f"(d[2]), "+f"(d[3])
        : "r"(a[0]), "r"(a[1]), "r"(a[2]), "r"(a[3]), "r"(b[0]), "r"(b[1]));
}

// ---------------------------------------------------------------------------
// Prep: fp32 -> fp16 convert of x
// ---------------------------------------------------------------------------
__global__ void convert_x_kernel(const float* __restrict__ x,
                                 __half* __restrict__ o) {
    size_t i = ((size_t)blockIdx.x * 256 + threadIdx.x) * 4;
    float4 f = *reinterpret_cast<const float4*>(x + i);
    __half2 h0 = __floats2half2_rn(f.x, f.y);
    __half2 h1 = __floats2half2_rn(f.z, f.w);
    *reinterpret_cast<uint2*>(o + i) =
        make_uint2(*reinterpret_cast<uint32_t*>(&h0), *reinterpret_cast<uint32_t*>(&h1));
}

// ---------------------------------------------------------------------------
// Prep: per-v transpose [v][R][C] -> [v][C][R] + fp16 convert
// ---------------------------------------------------------------------------
__global__ void transpose_convert_kernel(const float* __restrict__ in,
                                         __half* __restrict__ o,
                                         int R, int C) {
    __shared__ float t[32][33];
    const int v = blockIdx.z;
    const float* src = in + (size_t)v * R * C;
    const size_t ob = (size_t)v * R * C;
    const int tx = threadIdx.x, ty = threadIdx.y;
    const int c = blockIdx.x * 32 + tx;
#pragma unroll
    for (int j = 0; j < 32; j += 8) {
        int r = blockIdx.y * 32 + ty + j;
        t[ty + j][tx] = src[(size_t)r * C + c];
    }
    __syncthreads();
    const int r2 = blockIdx.y * 32 + tx;  // output fast dim (R index)
#pragma unroll
    for (int j = 0; j < 32; j += 8) {
        int c2 = blockIdx.x * 32 + ty + j;  // output row (C index)
        o[ob + (size_t)c2 * R + r2] = __float2half_rn(t[tx][ty + j]);
    }
}

// ---------------------------------------------------------------------------
// Batched fp16 GEMM via mma.sync (fp32 accumulate):
//   D[128 x NT] = A[128 x K] * B[NT x K]^T  (per (m-block, v, n-block) CTA)
//   8 warps, warp grid WG_M x WG_N, warp tile (WM*16) x (WN*8)
//   Kc = 64 per chunk, 3-stage cp.async pipeline, SW128 swizzle, ldmatrix
// ---------------------------------------------------------------------------
template <int NT, int WG_M, int WG_N, int WM, int WN, bool RELU>
__global__ void __launch_bounds__(256) gemm_kernel(
    const __half* __restrict__ A, long long aVStride,
    const __half* __restrict__ B,
    int K, int Ndim, int nPerV,
    const float* __restrict__ bias,
    __half* __restrict__ O,
    float* __restrict__ out)
{
    static_assert(WG_M * WG_N == 8, "8 warps");
    static_assert(WG_M * WM * 16 == 128, "M tile 128");
    static_assert(WG_N * WN * 8 == NT, "N tile");
    static_assert(WN % 2 == 0, "B ldmatrix pairs");

    extern __shared__ __align__(1024) char smem[];
    const uint32_t sb = smem_u32(smem);
    const int tid = threadIdx.x, wid = tid >> 5, lane = tid & 31;
    const int v  = blockIdx.y / nPerV, nb = blockIdx.y % nPerV;
    const int m0 = blockIdx.x * 128;
    const int n0 = nb * NT;
    const int NC = K >> 6;                 // K chunks of 64

    constexpr int A_SZ = 128 * 128;        // bytes per A tile per stage (16KB)
    constexpr int B_SZ = NT * 128;
    constexpr int STG  = A_SZ + B_SZ;
    const uint32_t st[3] = { sb, sb + STG, sb + 2 * STG };

    const __half* A_ = A + (size_t)v * aVStride;
    const __half* B_ = B + ((size_t)v * Ndim + n0) * K;

    // ---- chunk loader: Kc=64 cols starting at kk into stage s ----
    auto load_chunk = [&](int s, int kk) {
        const uint32_t aS = st[s], bS = st[s] + A_SZ;
        for (int idx = tid; idx < 128 * 8; idx += 256) {
            int r = idx >> 3, u = idx & 7;
            uint32_t so = swz((uint32_t)(r * 128 + u * 16));
            cp16(aS + so, A_ + (size_t)(m0 + r) * K + kk + u * 8);
        }
        for (int idx = tid; idx < NT * 8; idx += 256) {
            int r = idx >> 3, u = idx & 7;
            uint32_t so = swz((uint32_t)(r * 128 + u * 16));
            cp16(bS + so, B_ + (size_t)r * K + kk + u * 8);
        }
        cp_commit();
    };

    // warp tile origin
    const int wm = (wid / WG_N) * (WM * 16);
    const int wn = (wid % WG_N) * (WN * 8);

    float d[WM][WN][4];
#pragma unroll
    for (int i = 0; i < WM; i++)
#pragma unroll
        for (int j = 0; j < WN; j++)
#pragma unroll
            for (int q = 0; q < 4; q++) d[i][j][q] = 0.0f;

    load_chunk(0, 0);
    load_chunk(1, 64);

    // A lane address pattern: row = base + (lane&15), k-half = lane>>4
    const int aRow = (lane & 15);
    const int aKh  = (lane >> 4) * 8;
    // B lane address pattern (x4 covers two n8 tiles)
    const int bRow = (lane & 7) + (((lane >> 4) & 1) << 3);
    const int bKh  = ((lane >> 3) & 1) * 8;

    for (int kc = 0; kc < NC; kc++) {
        const int s = kc % 3;
        if (kc + 2 <= NC) { cp_wait<1>(); } else { cp_wait<0>(); }
        __syncthreads();
        if (kc + 2 < NC) load_chunk((kc + 2) % 3, (kc + 2) * 64);

        const uint32_t aS = st[s], bS = st[s] + A_SZ;

#pragma unroll
        for (int ks = 0; ks < 4; ks++) {
            const int k0 = ks * 16;
            uint32_t af[WM][4], bf[WN][2];
#pragma unroll
            for (int i = 0; i < WM; i++) {
                uint32_t off = swz((uint32_t)((wm + aRow + i * 16) * 128 + (k0 + aKh) * 2));
                ldsm4(af[i][0], af[i][1], af[i][2], af[i][3], aS + off);
            }
#pragma unroll
            for (int j2 = 0; j2 < WN / 2; j2++) {
                uint32_t off = swz((uint32_t)((wn + bRow + j2 * 16) * 128 + (k0 + bKh) * 2));
                ldsm4(bf[2 * j2][0], bf[2 * j2][1], bf[2 * j2 + 1][0], bf[2 * j2 + 1][1], bS + off);
            }
#pragma unroll
            for (int i = 0; i < WM; i++)
#pragma unroll
                for (int j = 0; j < WN; j++) mma16816(d[i][j], af[i], bf[j]);
        }
    }

    // ---- epilogue (register fragments, canonical m16n8 D mapping) ----
    const int rBase = lane >> 2;         // 0..7
    const int cBase = (lane & 3) * 2;    // 0,2,4,6
#pragma unroll
    for (int j = 0; j < WN; j++) {
        const int n = n0 + wn + j * 8 + cBase;   // global n (even)
        float bv0 = 0.0f, bv1 = 0.0f;
        if (RELU) {
            bv0 = bias[(size_t)v * kH + n];
            bv1 = bias[(size_t)v * kH + n + 1];
        }
#pragma unroll
        for (int i = 0; i < WM; i++) {
#pragma unroll
            for (int half = 0; half < 2; half++) {
                const int m = m0 + wm + i * 16 + rBase + half * 8;
                float f0 = d[i][j][2 * half];
                float f1 = d[i][j][2 * half + 1];
                if (RELU) {
                    f0 = fmaxf(f0 + bv0, 0.0f);
                    f1 = fmaxf(f1 + bv1, 0.0f);
                    __half2 h2 = __floats2half2_rn(f0, f1);
                    size_t dst = ((size_t)v * kB + m) * kH + n;
                    *reinterpret_cast<uint32_t*>(O + dst) = *reinterpret_cast<uint32_t*>(&h2);
                } else {
                    size_t dst = (size_t)m * ((size_t)kV * kO) + (size_t)v * kO + n;
                    *reinterpret_cast<float2*>(out + dst) = make_float2(f0, f1);
                }
            }
        }
    }
}

// ---------------------------------------------------------------------------
// Launch
// ---------------------------------------------------------------------------
extern "C" void kernel_launch(void* const* d_in, const int* in_sizes, int n_in,
                              void* d_out, int out_size) {
    const float* x  = (const float*)d_in[0];
    const float* W1 = (const float*)d_in[1];
    const float* b1 = (const float*)d_in[2];
    const float* W2 = (const float*)d_in[3];
    const float* b2 = (const float*)d_in[4];
    const float* W3 = (const float*)d_in[5];
    float* out = (float*)d_out;

    void *pX, *pW1, *pW2, *pW3, *pH1, *pH2;
    cudaGetSymbolAddress(&pX,  g_X);
    cudaGetSymbolAddress(&pW1, g_W1);
    cudaGetSymbolAddress(&pW2, g_W2);
    cudaGetSymbolAddress(&pW3, g_W3);
    cudaGetSymbolAddress(&pH1, g_H1);
    cudaGetSymbolAddress(&pH2, g_H2);

    // smem: 3 stages * (16KB A + NT*128 B)
    constexpr int SMEM_BIG = 3 * (128 * 128 + 128 * 128);  // NT=128 -> 96KB
    constexpr int SMEM_SM  = 3 * (128 * 128 + 64 * 128);   // NT=64  -> 72KB
    cudaFuncSetAttribute((const void*)gemm_kernel<128, 2, 4, 4, 4, true>,
                         cudaFuncAttributeMaxDynamicSharedMemorySize, SMEM_BIG);
    cudaFuncSetAttribute((const void*)gemm_kernel<64, 4, 2, 2, 4, false>,
                         cudaFuncAttributeMaxDynamicSharedMemorySize, SMEM_SM);

    // prep: convert x, transpose+convert weights
    convert_x_kernel<<<(kB * kIN) / 1024, 256>>>(x, (__half*)pX);
    dim3 tb(32, 8);
    transpose_convert_kernel<<<dim3(kH / 32, kIN / 32, kV), tb>>>(W1, (__half*)pW1, kIN, kH);
    transpose_convert_kernel<<<dim3(kH / 32, kH / 32, kV), tb>>>(W2, (__half*)pW2, kH, kH);
    transpose_convert_kernel<<<dim3(kO / 32, kH / 32, kV), tb>>>(W3, (__half*)pW3, kH, kO);

    // layer 1: [4096,1024] x [48,512,1024]^T -> H1
    gemm_kernel<128, 2, 4, 4, 4, true><<<dim3(kB / 128, kV * (kH / 128)), 256, SMEM_BIG>>>(
        (const __half*)pX, 0LL, (const __half*)pW1,
        kIN, kH, kH / 128, b1, (__half*)pH1, nullptr);

    // layer 2: H1 x [48,512,512]^T -> H2
    gemm_kernel<128, 2, 4, 4, 4, true><<<dim3(kB / 128, kV * (kH / 128)), 256, SMEM_BIG>>>(
        (const __half*)pH1, (long long)kB * kH, (const __half*)pW2,
        kH, kH, kH / 128, b2, (__half*)pH2, nullptr);

    // layer 3: H2 x [48,64,512]^T -> out (fp32, no bias/relu)
    gemm_kernel<64, 4, 2, 2, 4, false><<<dim3(kB / 128, kV), 256, SMEM_SM>>>(
        (const __half*)pH2, (long long)kB * kH, (const __half*)pW3,
        kH, kO, 1, nullptr, nullptr, out);
}